// round 17
// baseline (speedup 1.0000x reference)
#include <cuda_runtime.h>
#include <cuda_fp16.h>
#include <cstdint>

// GPR-GNN sparse propagation, sm_103a (base-target PTX only — no tcgen05).
// R15: deferred hidden accumulation. Aggs write per-layer fp16 planes only;
// the last agg folds the full GPR sum (x0 + all planes + last acc) into d_out.
// fp16 HMMA GEMM (fp32 accum), dst-CSR gather, all unchanged from R13.

#define D 128
#define MAXN 50000
#define MAXE 800000
#define MAXL 8
#define TILE_M 128
#define SCAN_B 256

// ---- scratch (static device arrays; no allocation) ----
__device__ __align__(16) __half g_h[MAXN * D];            // h = x @ W + b (fp16)
__device__ __align__(16) __half g_xp[MAXL * MAXN * D];    // fp16 x planes (layer k -> slot k-1)
__device__ int   g_counts[MAXN];
__device__ int   g_cursor[MAXN];
__device__ int   g_rowptr[MAXN + 1];
__device__ int   g_bsum[1024];
__device__ __align__(16) int2 g_edge[MAXE];               // (src, bits(w)) sorted by dst
// Pre-swizzled fp16 W image (B = W^T as [n][k], smem tile layout):
__device__ __align__(16) __half g_W16[MAXL * D * D];

// =================================================================== helpers
__device__ __forceinline__ unsigned s2u(const void* ptr) {
    unsigned a;
    asm("{ .reg .u64 t; cvta.to.shared.u64 t, %1; cvt.u32.u64 %0, t; }" : "=r"(a) : "l"(ptr));
    return a;
}
__device__ __forceinline__ void ldsm4(unsigned* r, unsigned addr) {
    asm volatile("ldmatrix.sync.aligned.m8n8.x4.shared.b16 {%0,%1,%2,%3}, [%4];"
                 : "=r"(r[0]), "=r"(r[1]), "=r"(r[2]), "=r"(r[3]) : "r"(addr));
}
__device__ __forceinline__ void mma_f16(float* c, const unsigned* a, unsigned b0, unsigned b1) {
    asm volatile("mma.sync.aligned.m16n8k16.row.col.f32.f16.f16.f32 "
                 "{%0,%1,%2,%3}, {%4,%5,%6,%7}, {%8,%9}, {%0,%1,%2,%3};"
                 : "+f"(c[0]), "+f"(c[1]), "+f"(c[2]), "+f"(c[3])
                 : "r"(a[0]), "r"(a[1]), "r"(a[2]), "r"(a[3]), "r"(b0), "r"(b1));
}
// Swizzled byte offset of 16B chunk (row, chunk c) in a [rows][128] fp16 tile
// (256B/row, 16 chunks). chunk' = c ^ (row & 15) -> conflict-free ldmatrix.
__device__ __forceinline__ unsigned sw_off(int row, int c) {
    return (unsigned)(row * 256 + ((c ^ (row & 15)) << 4));
}

// ---------------------------------------------------------------- W pre-conv
__global__ void wconv_kernel(const float* __restrict__ W, int L) {
    int t = blockIdx.x * blockDim.x + threadIdx.x;
    int total = L * D * (D / 8);
    if (t >= total) return;
    int l = t / (D * D / 8);
    int rem = t % (D * D / 8);
    int n = rem / (D / 8);     // output column (B row)
    int g = rem % (D / 8);     // k-chunk of 8
    const float* Wl = W + (size_t)l * D * D;
    union { uint4 u; __half s[8]; } p;
    #pragma unroll
    for (int j = 0; j < 8; j++)
        p.s[j] = __float2half_rn(Wl[(g * 8 + j) * D + n]);
    unsigned off = sw_off(n, g);
    *(uint4*)((char*)(g_W16 + (size_t)l * D * D) + off) = p.u;
}

// ---------------------------------------------------------------- CSR build
__global__ void hist_kernel(const int* __restrict__ dst, int e) {
    int i = blockIdx.x * blockDim.x + threadIdx.x;
    if (i < e) atomicAdd(&g_counts[dst[i]], 1);
}
__global__ void local_scan_kernel(int n) {
    __shared__ int wsums[8];
    int b = blockIdx.x;
    int i = b * SCAN_B + threadIdx.x;
    int lane = threadIdx.x & 31, wid = threadIdx.x >> 5;
    int v = (i < n) ? g_counts[i] : 0;
    int s = v;
    #pragma unroll
    for (int o = 1; o < 32; o <<= 1) {
        int t = __shfl_up_sync(0xFFFFFFFFu, s, o);
        if (lane >= o) s += t;
    }
    if (lane == 31) wsums[wid] = s;
    __syncthreads();
    if (wid == 0) {
        int ws = (lane < 8) ? wsums[lane] : 0;
        #pragma unroll
        for (int o = 1; o < 8; o <<= 1) {
            int t = __shfl_up_sync(0xFFFFFFFFu, ws, o);
            if (lane >= o) ws += t;
        }
        if (lane < 8) wsums[lane] = ws;
    }
    __syncthreads();
    int excl = s - v + (wid > 0 ? wsums[wid - 1] : 0);
    if (i < n) g_rowptr[i] = excl;
    if (threadIdx.x == SCAN_B - 1) g_bsum[b] = excl + v;
}
__global__ void scanb_kernel(int nb, int n) {
    __shared__ int wsums[8];
    int t = threadIdx.x;
    int lane = t & 31, wid = t >> 5;
    int chunk = (nb + 255) / 256;
    int beg = t * chunk, end = min(beg + chunk, nb);
    int v = 0;
    for (int i = beg; i < end; i++) v += g_bsum[i];
    int s = v;
    #pragma unroll
    for (int o = 1; o < 32; o <<= 1) {
        int u = __shfl_up_sync(0xFFFFFFFFu, s, o);
        if (lane >= o) s += u;
    }
    if (lane == 31) wsums[wid] = s;
    __syncthreads();
    if (wid == 0) {
        int ws = (lane < 8) ? wsums[lane] : 0;
        #pragma unroll
        for (int o = 1; o < 8; o <<= 1) {
            int u = __shfl_up_sync(0xFFFFFFFFu, ws, o);
            if (lane >= o) ws += u;
        }
        if (lane < 8) wsums[lane] = ws;
    }
    __syncthreads();
    int excl = s - v + (wid > 0 ? wsums[wid - 1] : 0);
    for (int i = beg; i < end; i++) { int c = g_bsum[i]; g_bsum[i] = excl; excl += c; }
    if (t == 255) g_rowptr[n] = s + (wid > 0 ? wsums[wid - 1] : 0);
}
__global__ void addoff_kernel(int n) {
    int i = blockIdx.x * SCAN_B + threadIdx.x;
    if (i < n) {
        int r = g_rowptr[i] + g_bsum[blockIdx.x];
        g_rowptr[i] = r;
        g_cursor[i] = r;
    }
}
__global__ void scatter_kernel(const int* __restrict__ src, const int* __restrict__ dst,
                               const float* __restrict__ w, int e) {
    int i = blockIdx.x * blockDim.x + threadIdx.x;
    if (i < e) {
        int p = atomicAdd(&g_cursor[dst[i]], 1);
        g_edge[p] = make_int2(src[i], __float_as_int(w[i]));
    }
}

// ---------------------------------------------------------------- GEMM (HMMA)
// 128x128 tile, 8 warps (4m x 2n), warp = 32x64, single fp16 product.
// smem: A 32KB | W 32KB | bias 512B  -> 2 CTAs/SM.
#define SM_X    0
#define SM_B    32768
#define SM_BIAS 65536
#define SM_GEMM_TOTAL (65536 + 512 + 64)

__global__ void __launch_bounds__(256, 2)
gemm_hmma_kernel(const float* __restrict__ xin0, const float* __restrict__ bl,
                 int layer, int n) {
    extern __shared__ char smem[];
    unsigned sbase = s2u(smem);
    int tid = threadIdx.x;
    int row0 = blockIdx.x * TILE_M;

    if (tid < 32) ((float4*)(smem + SM_BIAS))[tid] = ((const float4*)bl)[tid];

    // stage pre-swizzled W image (identity copy, 2048 uint4)
    {
        const uint4* wg = (const uint4*)(g_W16 + (size_t)layer * D * D);
        uint4* ws = (uint4*)(smem + SM_B);
        #pragma unroll
        for (int i = tid; i < 2048; i += 256) ws[i] = wg[i];
    }

    // stage A tile: 128 rows x 16 chunks = 2048 chunks
    if (layer == 0) {
        // fp32 input -> fp16 convert
        const float4* X4 = (const float4*)xin0;
        #pragma unroll
        for (int it = 0; it < 8; it++) {
            int i = tid + 256 * it;
            int r = i >> 4, c = i & 15;
            int gr = row0 + r;
            float4 f0 = make_float4(0.f, 0.f, 0.f, 0.f), f1 = f0;
            if (gr < n) {
                f0 = X4[(size_t)gr * 32 + c * 2];
                f1 = X4[(size_t)gr * 32 + c * 2 + 1];
            }
            union { uint4 u; __half2 s[4]; } p;
            p.s[0] = __floats2half2_rn(f0.x, f0.y);
            p.s[1] = __floats2half2_rn(f0.z, f0.w);
            p.s[2] = __floats2half2_rn(f1.x, f1.y);
            p.s[3] = __floats2half2_rn(f1.z, f1.w);
            *(uint4*)(smem + SM_X + sw_off(r, c)) = p.u;
        }
    } else {
        // fp16 plane (layer-1) -> identity copy + swizzle
        const uint4* XH = (const uint4*)(g_xp + (size_t)(layer - 1) * MAXN * D);
        uint4 z = make_uint4(0, 0, 0, 0);
        #pragma unroll
        for (int it = 0; it < 8; it++) {
            int i = tid + 256 * it;
            int r = i >> 4, c = i & 15;
            int gr = row0 + r;
            uint4 vh = (gr < n) ? XH[(size_t)gr * 16 + c] : z;
            *(uint4*)(smem + SM_X + sw_off(r, c)) = vh;
        }
    }
    __syncthreads();

    int wid = tid >> 5, lane = tid & 31;
    int m0 = (wid >> 1) * 32;          // warp rows (2 m-tiles of 16)
    int n0 = (wid & 1) * 64;           // warp cols (8 n-tiles of 8)

    float c[2][8][4];
    #pragma unroll
    for (int mt = 0; mt < 2; mt++)
        #pragma unroll
        for (int t = 0; t < 8; t++) {
            c[mt][t][0] = 0.f; c[mt][t][1] = 0.f; c[mt][t][2] = 0.f; c[mt][t][3] = 0.f;
        }

    int arow = m0 + (lane & 15);
    int acsel = lane >> 4;
    int bn = n0 + ((lane >> 4) << 3) + (lane & 7);
    int bcsel = (lane >> 3) & 1;

    #pragma unroll
    for (int kt = 0; kt < 8; kt++) {
        unsigned a[2][4];
        #pragma unroll
        for (int mt = 0; mt < 2; mt++)
            ldsm4(a[mt], sbase + SM_X + sw_off(arow + 16 * mt, kt * 2 + acsel));
        #pragma unroll
        for (int p = 0; p < 4; p++) {
            int nb = bn + p * 16;
            unsigned bfr[4];
            ldsm4(bfr, sbase + SM_B + sw_off(nb, kt * 2 + bcsel));
            #pragma unroll
            for (int mt = 0; mt < 2; mt++) {
                mma_f16(c[mt][2 * p],     a[mt], bfr[0], bfr[1]);
                mma_f16(c[mt][2 * p + 1], a[mt], bfr[2], bfr[3]);
            }
        }
    }

    // epilogue: + bias, store fp16 h
    const float* sb = (const float*)(smem + SM_BIAS);
    #pragma unroll
    for (int mt = 0; mt < 2; mt++) {
        int ra = row0 + m0 + mt * 16 + (lane >> 2);
        int rb = ra + 8;
        bool va = ra < n, vb = rb < n;
        __half* hra = g_h + (size_t)ra * D;
        __half* hrb = g_h + (size_t)rb * D;
        #pragma unroll
        for (int t = 0; t < 8; t++) {
            int col = n0 + t * 8 + (lane & 3) * 2;
            float b0 = sb[col], b1 = sb[col + 1];
            if (va) *(__half2*)(hra + col) = __floats2half2_rn(c[mt][t][0] + b0, c[mt][t][1] + b1);
            if (vb) *(__half2*)(hrb + col) = __floats2half2_rn(c[mt][t][2] + b0, c[mt][t][3] + b1);
        }
    }
}

// ---------------------------------------------------------------- aggregation
// One warp per dst node. Gather h rows (fp16, 256B); fp32 accumulate; MLP=4.
// layer < last: write fp16 plane only (no hidden traffic).
// layer == last: out = temp[0]*x0 + sum_{k=1..L-1} temp[k]*plane_k + temp[L]*acc.
__global__ void agg_kernel(const float* __restrict__ x0, float* __restrict__ out,
                           const float* __restrict__ temp, int layer, int L, int n) {
    int warp = (blockIdx.x * blockDim.x + threadIdx.x) >> 5;
    int lane = threadIdx.x & 31;
    if (warp >= n) return;

    int beg = g_rowptr[warp];
    int end = g_rowptr[warp + 1];

    float4 acc = make_float4(0.f, 0.f, 0.f, 0.f);
    const uint2* H2 = reinterpret_cast<const uint2*>(g_h);   // 32 uint2 per row
    int e = beg;
    for (; e + 4 <= end; e += 4) {
        int2 e0 = g_edge[e];
        int2 e1 = g_edge[e + 1];
        int2 e2 = g_edge[e + 2];
        int2 e3 = g_edge[e + 3];
        uint2 r0 = H2[(size_t)e0.x * 32 + lane];
        uint2 r1 = H2[(size_t)e1.x * 32 + lane];
        uint2 r2 = H2[(size_t)e2.x * 32 + lane];
        uint2 r3 = H2[(size_t)e3.x * 32 + lane];
        float w0 = __int_as_float(e0.y), w1 = __int_as_float(e1.y);
        float w2 = __int_as_float(e2.y), w3 = __int_as_float(e3.y);
        float2 p0 = __half22float2(*(const __half2*)&r0.x);
        float2 q0 = __half22float2(*(const __half2*)&r0.y);
        float2 p1 = __half22float2(*(const __half2*)&r1.x);
        float2 q1 = __half22float2(*(const __half2*)&r1.y);
        float2 p2 = __half22float2(*(const __half2*)&r2.x);
        float2 q2 = __half22float2(*(const __half2*)&r2.y);
        float2 p3 = __half22float2(*(const __half2*)&r3.x);
        float2 q3 = __half22float2(*(const __half2*)&r3.y);
        acc.x += p0.x * w0 + p1.x * w1 + p2.x * w2 + p3.x * w3;
        acc.y += p0.y * w0 + p1.y * w1 + p2.y * w2 + p3.y * w3;
        acc.z += q0.x * w0 + q1.x * w1 + q2.x * w2 + q3.x * w3;
        acc.w += q0.y * w0 + q1.y * w1 + q2.y * w2 + q3.y * w3;
    }
    for (; e < end; e++) {
        int2 e0 = g_edge[e];
        uint2 r0 = H2[(size_t)e0.x * 32 + lane];
        float w0 = __int_as_float(e0.y);
        float2 p0 = __half22float2(*(const __half2*)&r0.x);
        float2 q0 = __half22float2(*(const __half2*)&r0.y);
        acc.x += p0.x * w0;
        acc.y += p0.y * w0;
        acc.z += q0.x * w0;
        acc.w += q0.y * w0;
    }
    acc.x = fmaxf(acc.x, 0.f);
    acc.y = fmaxf(acc.y, 0.f);
    acc.z = fmaxf(acc.z, 0.f);
    acc.w = fmaxf(acc.w, 0.f);

    int idx = warp * 32 + lane;

    if (layer != L - 1) {
        // emit fp16 plane only (slot = layer)
        union { uint2 u; __half2 s[2]; } p;
        p.s[0] = __floats2half2_rn(acc.x, acc.y);
        p.s[1] = __floats2half2_rn(acc.z, acc.w);
        reinterpret_cast<uint2*>(g_xp + (size_t)layer * MAXN * D)[idx] = p.u;
        return;
    }

    // last layer: fold full GPR sum into out
    float t0 = __ldg(temp);
    float tl = __ldg(temp + L);
    float4 xv = reinterpret_cast<const float4*>(x0)[idx];
    float4 hv;
    hv.x = t0 * xv.x + tl * acc.x;
    hv.y = t0 * xv.y + tl * acc.y;
    hv.z = t0 * xv.z + tl * acc.z;
    hv.w = t0 * xv.w + tl * acc.w;
    for (int k = 1; k < L; k++) {
        float tk = __ldg(temp + k);
        uint2 pu = reinterpret_cast<const uint2*>(g_xp + (size_t)(k - 1) * MAXN * D)[idx];
        float2 pa = __half22float2(*(const __half2*)&pu.x);
        float2 pb = __half22float2(*(const __half2*)&pu.y);
        hv.x += tk * pa.x;
        hv.y += tk * pa.y;
        hv.z += tk * pb.x;
        hv.w += tk * pb.y;
    }
    reinterpret_cast<float4*>(out)[idx] = hv;
}

// ---------------------------------------------------------------- launch
extern "C" void kernel_launch(void* const* d_in, const int* in_sizes, int n_in,
                              void* d_out, int out_size) {
    const float* x    = (const float*)d_in[0];
    const float* w    = (const float*)d_in[1];
    const int*   src  = (const int*)d_in[2];
    const int*   dst  = (const int*)d_in[3];
    const float* W    = (const float*)d_in[4];
    const float* b    = (const float*)d_in[5];
    const float* temp = (const float*)d_in[6];

    int N = in_sizes[0] / D;
    int E = in_sizes[1];
    int L = in_sizes[4] / (D * D);
    if (L > MAXL) L = MAXL;
    float* out = (float*)d_out;

    // W fp16 convert + pre-swizzle (tiny, once per replay)
    wconv_kernel<<<(L * D * (D / 8) + 255) / 256, 256>>>(W, L);

    // CSR build (once per replay, reused by all L layers)
    int nbl = (N + SCAN_B - 1) / SCAN_B;
    void* counts_ptr = nullptr;
    cudaGetSymbolAddress(&counts_ptr, g_counts);
    cudaMemsetAsync(counts_ptr, 0, (size_t)N * sizeof(int));
    hist_kernel<<<(E + 255) / 256, 256>>>(dst, E);
    local_scan_kernel<<<nbl, SCAN_B>>>(N);
    scanb_kernel<<<1, 256>>>(nbl, N);
    addoff_kernel<<<nbl, SCAN_B>>>(N);
    scatter_kernel<<<(E + 255) / 256, 256>>>(src, dst, w, E);

    cudaFuncSetAttribute(gemm_hmma_kernel, cudaFuncAttributeMaxDynamicSharedMemorySize,
                         SM_GEMM_TOTAL);

    int ntiles = (N + TILE_M - 1) / TILE_M;
    for (int l = 0; l < L; l++) {
        gemm_hmma_kernel<<<ntiles, 256, SM_GEMM_TOTAL>>>(x, b + (size_t)l * D, l, N);
        agg_kernel<<<(N * 32 + 255) / 256, 256>>>(x, out, temp, l, L, N);
    }
}